// round 7
// baseline (speedup 1.0000x reference)
#include <cuda_runtime.h>
#include <cuda_bf16.h>
#include <stdint.h>

#define BATCH 16384
#define DIMQ  512
#define ZPD   1024
#define HID   256
#define DTC   0.1f

#define BM 64
#define XPITCH 528                        // 256 bf16 = 512B + 16B pad
#define X_OFF 0                           // h1, then d1 (in-place)
#define XSZ (BM * XPITCH)                 // 33792
#define Y_OFF XSZ                         // d2
#define ASTG_OFF (2 * XSZ)                // 67584
#define AROW 144                          // 64 k * 2B = 128B + 16B pad
#define ACHUNK (BM * AROW)                // 9216 per k64 chunk
#define SMEM_SZ (ASTG_OFF + 4 * ACHUNK)   // 104448 -> 2 CTAs/SM

// ---------------- device globals (no allocs allowed) ----------------
__device__ float         g_zp [BATCH * ZPD];     // fp32 master [q|p]
__device__ __nv_bfloat16 g_zpb[BATCH * ZPD];     // bf16 mirror (MMA operand)
__device__ __nv_bfloat16 g_W1t[HID * ZPD];       // W1^T [256][1024]
__device__ __nv_bfloat16 g_W1d[ZPD * HID];       // W1   [1024][256]
__device__ __nv_bfloat16 g_W2t[HID * HID];       // W2^T
__device__ __nv_bfloat16 g_W2d[HID * HID];       // W2

// ---------------- helpers ----------------
__device__ __forceinline__ uint32_t smem_u32(const void* p) {
    uint32_t a;
    asm("{ .reg .u64 t; cvta.to.shared.u64 t, %1; cvt.u32.u64 %0, t; }" : "=r"(a) : "l"(p));
    return a;
}
__device__ __forceinline__ float tanh_fast(float x) {
    float y; asm("tanh.approx.f32 %0, %1;" : "=f"(y) : "f"(x)); return y;
}
__device__ __forceinline__ void cp16(uint32_t s, const void* g) {
    asm volatile("cp.async.cg.shared.global [%0], [%1], 16;" :: "r"(s), "l"(g) : "memory");
}
__device__ __forceinline__ void ldsm4(uint32_t* r, uint32_t a) {
    asm volatile("ldmatrix.sync.aligned.m8n8.x4.shared.b16 {%0,%1,%2,%3}, [%4];"
                 : "=r"(r[0]), "=r"(r[1]), "=r"(r[2]), "=r"(r[3]) : "r"(a));
}
__device__ __forceinline__ void mma16816(float* c, const uint32_t* a, const uint32_t* b) {
    asm volatile("mma.sync.aligned.m16n8k16.row.col.f32.bf16.bf16.f32 "
                 "{%0,%1,%2,%3}, {%4,%5,%6,%7}, {%8,%9}, {%0,%1,%2,%3};"
                 : "+f"(c[0]), "+f"(c[1]), "+f"(c[2]), "+f"(c[3])
                 : "r"(a[0]), "r"(a[1]), "r"(a[2]), "r"(a[3]), "r"(b[0]), "r"(b[1]));
}
__device__ __forceinline__ __nv_bfloat162 pack_bf2(float a, float b) {
    return __halves2bfloat162(__float2bfloat16_rn(a), __float2bfloat16_rn(b));
}
// B fragment pair (two n8 tiles, one k16 step) loaded straight from gmem.
// b[0],b[1]: n-tile nb..nb+7 (k 0-7, 8-15); b[2],b[3]: n-tile nb+8..nb+15.
__device__ __forceinline__ void ldgB(uint32_t b[4], const __nv_bfloat16* __restrict__ W,
                                     int stride, int nb, int k, int lane) {
    const uint32_t* p0 = (const uint32_t*)(W + (size_t)(nb + (lane >> 2)) * stride
                                             + k + 2 * (lane & 3));
    const uint32_t* p1 = (const uint32_t*)((const __nv_bfloat16*)p0 + 8 * stride);
    b[0] = __ldg(p0);
    b[1] = __ldg(p0 + 4);      // +8 bf16 = +16B
    b[2] = __ldg(p1);
    b[3] = __ldg(p1 + 4);
}

#define ZERO_ACC(acc)                                                           \
    _Pragma("unroll") for (int _i = 0; _i < 4; _i++)                            \
    _Pragma("unroll") for (int _j = 0; _j < 4; _j++)                            \
    _Pragma("unroll") for (int _d = 0; _d < 4; _d++) (acc)[_i][_j][_d] = 0.f;

// ---------------------------------------------------------------------------
// Stage 1: acc[64 x n32/warp] = zp_tile[64 x 1024] @ W1t^T, A via 4-deep
// cp.async pipeline (one __syncthreads per k64 chunk), B via direct LDG.
// ---------------------------------------------------------------------------
__device__ __forceinline__ void stage1_gemm(
    uint32_t sb, const __nv_bfloat16* __restrict__ Agm,
    const __nv_bfloat16* __restrict__ Bgm, float (&acc)[4][4][4], int tid)
{
    const int lane = tid & 31, wn = tid >> 5;
    ZERO_ACC(acc);

    auto fill = [&](int s, int c) {
        const uint32_t stg = sb + ASTG_OFF + s * ACHUNK;
        #pragma unroll
        for (int r = 0; r < 2; r++) {
            const int i = tid + r * 256;            // 512 16B-chunks
            const int row = i >> 3, ch = i & 7;
            cp16(stg + row * AROW + ch * 16, Agm + (size_t)row * ZPD + c * 64 + ch * 8);
        }
        asm volatile("cp.async.commit_group;" ::: "memory");
    };

    fill(0, 0); fill(1, 1); fill(2, 2);

    #pragma unroll 1
    for (int c = 0; c < 16; c++) {
        const int rem = 15 - c;
        if (rem >= 2)      asm volatile("cp.async.wait_group 2;" ::: "memory");
        else if (rem == 1) asm volatile("cp.async.wait_group 1;" ::: "memory");
        else               asm volatile("cp.async.wait_group 0;" ::: "memory");
        __syncthreads();
        if (c + 3 < 16) fill((c + 3) & 3, c + 3);   // post-sync: reuse is race-free

        const uint32_t ab = sb + ASTG_OFF + (c & 3) * ACHUNK;
        #pragma unroll
        for (int ks = 0; ks < 4; ks++) {
            uint32_t a[4][4], b[2][4];
            #pragma unroll
            for (int mt = 0; mt < 4; mt++)
                ldsm4(a[mt], ab + (mt * 16 + (lane & 15)) * AROW
                              + ((lane >> 4) << 4) + ks * 32);
            #pragma unroll
            for (int p = 0; p < 2; p++)
                ldgB(b[p], Bgm, ZPD, wn * 32 + p * 16, c * 64 + ks * 16, lane);
            #pragma unroll
            for (int mt = 0; mt < 4; mt++)
                #pragma unroll
                for (int p = 0; p < 2; p++) {
                    mma16816(acc[mt][2 * p],     a[mt], &b[p][0]);
                    mma16816(acc[mt][2 * p + 1], a[mt], &b[p][2]);
                }
        }
    }
}

// ---------------------------------------------------------------------------
// Stages 2-4: A resident in smem (XPITCH rows), B via direct LDG. NO barriers.
// ---------------------------------------------------------------------------
__device__ __forceinline__ void gemm_res(
    uint32_t aBase, const __nv_bfloat16* __restrict__ Bgm,
    float (&acc)[4][4][4], int lane, int wn)
{
    ZERO_ACC(acc);
    #pragma unroll 2
    for (int kt = 0; kt < 16; kt++) {
        uint32_t a[4][4], b[2][4];
        #pragma unroll
        for (int mt = 0; mt < 4; mt++)
            ldsm4(a[mt], aBase + (mt * 16 + (lane & 15)) * XPITCH
                          + ((lane >> 4) << 4) + kt * 32);
        #pragma unroll
        for (int p = 0; p < 2; p++)
            ldgB(b[p], Bgm, HID, wn * 32 + p * 16, kt * 16, lane);
        #pragma unroll
        for (int mt = 0; mt < 4; mt++)
            #pragma unroll
            for (int p = 0; p < 2; p++) {
                mma16816(acc[mt][2 * p],     a[mt], &b[p][0]);
                mma16816(acc[mt][2 * p + 1], a[mt], &b[p][2]);
            }
    }
}

#define EPI_BEGIN                                                               \
    _Pragma("unroll") for (int mt = 0; mt < 4; mt++)                            \
    _Pragma("unroll") for (int i2 = 0; i2 < 2; i2++) {                          \
        const int m = mt * 16 + i2 * 8 + (lane >> 2);                           \
        _Pragma("unroll") for (int nt = 0; nt < 4; nt++) {                      \
            const int n = wn * 32 + nt * 8 + 2 * (lane & 3);                    \
            const float v0 = acc[mt][nt][i2 * 2], v1 = acc[mt][nt][i2 * 2 + 1];
#define EPI_END }}

// ---------------------------------------------------------------------------
// Fused gradH + leapfrog: one CTA owns 64 batch rows end-to-end.
// Warp layout: 8 warps = 8 n-slices (n32), each spans all 64 m rows.
// ---------------------------------------------------------------------------
__global__ void __launch_bounds__(256, 2) fused_grad(
    const float* __restrict__ b1, const float* __restrict__ b2,
    const float* __restrict__ W3, int qpOff, int colBase, float coef)
{
    extern __shared__ char smem[];
    const uint32_t sb = smem_u32(smem);
    const int tid = threadIdx.x, lane = tid & 31, wn = tid >> 5;
    const int m0 = blockIdx.x * BM;

    float acc[4][4][4];

    // Stage 1: h1 = tanh(zp @ W1 + b1) -> X
    stage1_gemm(sb, g_zpb + (size_t)m0 * ZPD, g_W1t, acc, tid);
    EPI_BEGIN
        const float t0 = tanh_fast(v0 + __ldg(b1 + n));
        const float t1 = tanh_fast(v1 + __ldg(b1 + n + 1));
        *(__nv_bfloat162*)(smem + X_OFF + m * XPITCH + n * 2) = pack_bf2(t0, t1);
    EPI_END
    __syncthreads();

    // Stage 2: d2 = (1 - tanh(h1@W2 + b2)^2) * W3 -> Y
    gemm_res(sb + X_OFF, g_W2t, acc, lane, wn);
    EPI_BEGIN
        const float t0 = tanh_fast(v0 + __ldg(b2 + n));
        const float t1 = tanh_fast(v1 + __ldg(b2 + n + 1));
        const float r0 = (1.0f - t0 * t0) * __ldg(W3 + n);
        const float r1 = (1.0f - t1 * t1) * __ldg(W3 + n + 1);
        *(__nv_bfloat162*)(smem + Y_OFF + m * XPITCH + n * 2) = pack_bf2(r0, r1);
    EPI_END
    __syncthreads();

    // Stage 3: d1 = (d2 @ W2^T) * (1 - h1^2) -> X in-place (owner-thread rmw)
    gemm_res(sb + Y_OFF, g_W2d, acc, lane, wn);
    EPI_BEGIN
        __nv_bfloat162* xp = (__nv_bfloat162*)(smem + X_OFF + m * XPITCH + n * 2);
        const __nv_bfloat162 hh = *xp;
        const float h0 = __bfloat162float(hh.x), h1v = __bfloat162float(hh.y);
        *xp = pack_bf2(v0 * (1.0f - h0 * h0), v1 * (1.0f - h1v * h1v));
    EPI_END
    __syncthreads();

    // Stage 4: g-half = d1 @ W1[qpOff..]^T, fused leapfrog zp update.
    // Two passes over n' halves; X is read-only here -> no sync between passes.
    #pragma unroll 1
    for (int pass = 0; pass < 2; pass++) {
        gemm_res(sb + X_OFF, g_W1d + (size_t)(qpOff + pass * 256) * HID, acc, lane, wn);
        EPI_BEGIN
            const size_t o = (size_t)(m0 + m) * ZPD + colBase + pass * 256 + n;
            float2 z = *(float2*)(g_zp + o);
            z.x += coef * v0;
            z.y += coef * v1;
            *(float2*)(g_zp + o) = z;
            *(__nv_bfloat162*)(g_zpb + o) = pack_bf2(z.x, z.y);
        EPI_END
    }
}

// ---------------- small kernels ----------------
__global__ void __launch_bounds__(256) prep_weights(const float* __restrict__ W1,
                                                    const float* __restrict__ W2)
{
    const int idx = blockIdx.x * 256 + threadIdx.x;     // 0 .. 262143
    {
        const int k = idx >> 8, n = idx & 255;
        const __nv_bfloat16 v = __float2bfloat16_rn(W1[idx]);
        g_W1d[idx] = v;
        g_W1t[n * ZPD + k] = v;
    }
    if (idx < HID * HID) {
        const int k = idx >> 8, n = idx & 255;
        const __nv_bfloat16 v = __float2bfloat16_rn(W2[idx]);
        g_W2d[idx] = v;
        g_W2t[n * HID + k] = v;
    }
}

__global__ void __launch_bounds__(256) init_zp(const float* __restrict__ z)
{
    const int i = blockIdx.x * 256 + threadIdx.x;       // over BATCH*DIMQ/4
    const int m = i / (DIMQ / 4);
    const int c = (i % (DIMQ / 4)) * 4;
    const float4 zv = *(const float4*)&z[(size_t)m * DIMQ + c];
    const size_t oq = (size_t)m * ZPD + c;
    const size_t op = oq + DIMQ;
    *(float4*)&g_zp[oq] = zv;
    *(float4*)&g_zp[op] = make_float4(0.f, 0.f, 0.f, 0.f);
    __nv_bfloat162 b01 = pack_bf2(zv.x, zv.y), b23 = pack_bf2(zv.z, zv.w);
    *(uint2*)&g_zpb[oq] = make_uint2(*(uint32_t*)&b01, *(uint32_t*)&b23);
    *(uint2*)&g_zpb[op] = make_uint2(0u, 0u);
}

__global__ void __launch_bounds__(256) write_out(float* __restrict__ out)
{
    const int i = blockIdx.x * 256 + threadIdx.x;
    const int m = i / (DIMQ / 4);
    const int c = (i % (DIMQ / 4)) * 4;
    *(float4*)&out[(size_t)m * DIMQ + c] = *(const float4*)&g_zp[(size_t)m * ZPD + c];
}

// ---------------- launcher ----------------
extern "C" void kernel_launch(void* const* d_in, const int* in_sizes, int n_in,
                              void* d_out, int out_size)
{
    const float* z  = (const float*)d_in[0];
    const float* W1 = (const float*)d_in[1];
    const float* b1 = (const float*)d_in[2];
    const float* W2 = (const float*)d_in[3];
    const float* b2 = (const float*)d_in[4];
    const float* W3 = (const float*)d_in[5];
    // d_in[6] = b3: constant, no gradient contribution.
    float* out = (float*)d_out;

    cudaFuncSetAttribute(fused_grad, cudaFuncAttributeMaxDynamicSharedMemorySize, SMEM_SZ);

    const dim3 blk(256);
    const dim3 grid_cp((BATCH * DIMQ / 4) / 256);
    const dim3 grid_f(BATCH / BM);          // 256 CTAs -> 2 per SM

    init_zp<<<grid_cp, blk>>>(z);
    prep_weights<<<ZPD * HID / 256, blk>>>(W1, W2);

    for (int step = 0; step < 3; step++) {
        // call 0: p -= 0.5*dt * g_q   (g_q: W1 rows 0..511 -> zp cols 512..1023)
        fused_grad<<<grid_f, blk, SMEM_SZ>>>(b1, b2, W3, 0, DIMQ, -0.5f * DTC);
        // call 1: q += dt * g_p       (g_p: W1 rows 512..1023 -> zp cols 0..511)
        fused_grad<<<grid_f, blk, SMEM_SZ>>>(b1, b2, W3, DIMQ, 0, DTC);
        // call 2: p -= 0.5*dt * g_q
        fused_grad<<<grid_f, blk, SMEM_SZ>>>(b1, b2, W3, 0, DIMQ, -0.5f * DTC);
    }
    write_out<<<grid_cp, blk>>>(out);
}

// round 8
// speedup vs baseline: 1.5378x; 1.5378x over previous
#include <cuda_runtime.h>
#include <cuda_bf16.h>
#include <stdint.h>

#define BATCH 16384
#define DIMQ  512
#define ZPD   1024
#define HID   256
#define DTC   0.1f

#define BM 64
#define XPITCH 528                        // 256 bf16 = 512B + 16B pad (ldsm conflict-free)
#define X_OFF 0                           // h1, then d1 (in-place), 33792 B
#define XSZ (BM * XPITCH)
#define Y_OFF XSZ                         // d2 (stages 2-4); stage-1 staging overlay
#define STG1_CHUNK 25600                  // A 64x80 (5120) + B 256x80 (20480)
#define STG1_B 5120
#define BSTG_OFF (2 * XSZ)                // 67584: per-warp B buffers (stages 2-4)
#define WBUF 2560                         // 32 rows x 80 B
#define SMEM_SZ (Y_OFF + 3 * STG1_CHUNK)  // 110592 -> 2 CTAs/SM

// ---------------- device globals (no allocs allowed) ----------------
__device__ float         g_zp [BATCH * ZPD];     // fp32 master [q|p]
__device__ __nv_bfloat16 g_zpb[BATCH * ZPD];     // bf16 mirror (MMA operand)
__device__ __nv_bfloat16 g_W1t[HID * ZPD];       // W1^T [256][1024]
__device__ __nv_bfloat16 g_W1d[ZPD * HID];       // W1   [1024][256]
__device__ __nv_bfloat16 g_W2t[HID * HID];       // W2^T
__device__ __nv_bfloat16 g_W2d[HID * HID];       // W2

// ---------------- helpers ----------------
__device__ __forceinline__ uint32_t smem_u32(const void* p) {
    uint32_t a;
    asm("{ .reg .u64 t; cvta.to.shared.u64 t, %1; cvt.u32.u64 %0, t; }" : "=r"(a) : "l"(p));
    return a;
}
__device__ __forceinline__ float tanh_fast(float x) {
    float y; asm("tanh.approx.f32 %0, %1;" : "=f"(y) : "f"(x)); return y;
}
__device__ __forceinline__ void cp16(uint32_t s, const void* g) {
    asm volatile("cp.async.cg.shared.global [%0], [%1], 16;" :: "r"(s), "l"(g) : "memory");
}
__device__ __forceinline__ void cp_commit() {
    asm volatile("cp.async.commit_group;" ::: "memory");
}
__device__ __forceinline__ void ldsm4(uint32_t* r, uint32_t a) {
    asm volatile("ldmatrix.sync.aligned.m8n8.x4.shared.b16 {%0,%1,%2,%3}, [%4];"
                 : "=r"(r[0]), "=r"(r[1]), "=r"(r[2]), "=r"(r[3]) : "r"(a));
}
__device__ __forceinline__ void mma16816(float* c, const uint32_t* a, const uint32_t* b) {
    asm volatile("mma.sync.aligned.m16n8k16.row.col.f32.bf16.bf16.f32 "
                 "{%0,%1,%2,%3}, {%4,%5,%6,%7}, {%8,%9}, {%0,%1,%2,%3};"
                 : "+f"(c[0]), "+f"(c[1]), "+f"(c[2]), "+f"(c[3])
                 : "r"(a[0]), "r"(a[1]), "r"(a[2]), "r"(a[3]), "r"(b[0]), "r"(b[1]));
}
__device__ __forceinline__ __nv_bfloat162 pack_bf2(float a, float b) {
    return __halves2bfloat162(__float2bfloat16_rn(a), __float2bfloat16_rn(b));
}

#define ZERO_ACC(acc)                                                           \
    _Pragma("unroll") for (int _i = 0; _i < 4; _i++)                            \
    _Pragma("unroll") for (int _j = 0; _j < 4; _j++)                            \
    _Pragma("unroll") for (int _d = 0; _d < 4; _d++) (acc)[_i][_j][_d] = 0.f;

// consume one k32 chunk: A from (abase, apitch), B from warp slice (bbase, 80B rows)
__device__ __forceinline__ void consume_k32(
    uint32_t abase, int apitch, uint32_t bbase,
    float (&acc)[4][4][4], int lane)
{
    #pragma unroll
    for (int kt = 0; kt < 2; kt++) {
        uint32_t a[4][4], b[2][4];
        #pragma unroll
        for (int mt = 0; mt < 4; mt++)
            ldsm4(a[mt], abase + (mt * 16 + (lane & 15)) * apitch
                          + ((lane >> 4) << 4) + kt * 32);
        #pragma unroll
        for (int p = 0; p < 2; p++)
            ldsm4(b[p], bbase + (p * 16 + ((lane >> 4) << 3) + (lane & 7)) * 80
                         + (((lane >> 3) & 1) << 4) + kt * 32);
        #pragma unroll
        for (int mt = 0; mt < 4; mt++)
            #pragma unroll
            for (int p = 0; p < 2; p++) {
                mma16816(acc[mt][2 * p],     a[mt], &b[p][0]);
                mma16816(acc[mt][2 * p + 1], a[mt], &b[p][2]);
            }
    }
}

// ---------------------------------------------------------------------------
// Stage 1: acc = zp_tile[64 x 1024] @ W1t^T. Joint A+B k32 chunks, 3-deep
// cp.async pipeline, ONE __syncthreads per chunk.
// ---------------------------------------------------------------------------
__device__ __forceinline__ void stage1_gemm(
    uint32_t sb, const __nv_bfloat16* __restrict__ Agm,
    float (&acc)[4][4][4], int tid)
{
    const int lane = tid & 31, wn = tid >> 5;
    ZERO_ACC(acc);

    auto fill = [&](int s, int c) {
        const uint32_t stg = sb + Y_OFF + s * STG1_CHUNK;
        {   // A: 64 rows x 4 x 16B = 256 units, 1/thread
            const int row = tid >> 2, ch = tid & 3;
            cp16(stg + row * 80 + ch * 16, Agm + (size_t)row * ZPD + c * 32 + ch * 8);
        }
        #pragma unroll
        for (int r = 0; r < 4; r++) {   // B: 256 rows x 4 units, 4/thread
            const int u = r * 256 + tid;
            const int row = u >> 2, ch = u & 3;
            cp16(stg + STG1_B + row * 80 + ch * 16,
                 g_W1t + (size_t)row * ZPD + c * 32 + ch * 8);
        }
        cp_commit();
    };

    fill(0, 0); fill(1, 1);
    #pragma unroll 1
    for (int c = 0; c < 32; c++) {
        if (c < 31) asm volatile("cp.async.wait_group 1;" ::: "memory");
        else        asm volatile("cp.async.wait_group 0;" ::: "memory");
        __syncthreads();
        if (c + 2 < 32) { int s = (c + 2) % 3; fill(s, c + 2); }
        const uint32_t ab = sb + Y_OFF + (c % 3) * STG1_CHUNK;
        consume_k32(ab, 80, ab + STG1_B + (wn * 32) * 80, acc, lane);
    }
}

// ---------------------------------------------------------------------------
// Stages 2-4: A resident in smem (XPITCH rows), B via WARP-LOCAL cp.async
// double buffer. NO CTA barriers.
// ---------------------------------------------------------------------------
__device__ __forceinline__ void gemm_res(
    uint32_t sb, uint32_t aOff, const __nv_bfloat16* __restrict__ W,
    float (&acc)[4][4][4], int lane, int wn)
{
    ZERO_ACC(acc);
    const uint32_t wb = sb + BSTG_OFF + wn * 2 * WBUF;
    const int n0w = wn * 32;

    auto fillB = [&](int s, int c) {
        const uint32_t stg = wb + s * WBUF;
        #pragma unroll
        for (int r = 0; r < 4; r++) {   // 32 rows x 4 x 16B = 128 units, 4/lane
            const int u = r * 32 + lane;
            const int row = u >> 2, ch = u & 3;
            cp16(stg + row * 80 + ch * 16, W + (size_t)(n0w + row) * HID + c * 32 + ch * 8);
        }
        cp_commit();
    };

    fillB(0, 0);
    #pragma unroll 1
    for (int c = 0; c < 8; c++) {
        if (c + 1 < 8) {
            fillB((c + 1) & 1, c + 1);
            asm volatile("cp.async.wait_group 1;" ::: "memory");
        } else {
            asm volatile("cp.async.wait_group 0;" ::: "memory");
        }
        __syncwarp();
        consume_k32(sb + aOff + c * 64, XPITCH, wb + (c & 1) * WBUF, acc, lane);
    }
}

#define EPI_BEGIN                                                               \
    _Pragma("unroll") for (int mt = 0; mt < 4; mt++)                            \
    _Pragma("unroll") for (int i2 = 0; i2 < 2; i2++) {                          \
        const int m = mt * 16 + i2 * 8 + (lane >> 2);                           \
        _Pragma("unroll") for (int nt = 0; nt < 4; nt++) {                      \
            const int n = wn * 32 + nt * 8 + 2 * (lane & 3);                    \
            const float v0 = acc[mt][nt][i2 * 2], v1 = acc[mt][nt][i2 * 2 + 1];
#define EPI_END }}

// ---------------------------------------------------------------------------
// Mega-kernel: one CTA owns 64 batch rows through ALL 9 gradH calls.
// ---------------------------------------------------------------------------
__global__ void __launch_bounds__(256, 2) leapfrog_all(
    const float* __restrict__ b1, const float* __restrict__ b2,
    const float* __restrict__ W3)
{
    extern __shared__ char smem[];
    const uint32_t sb = smem_u32(smem);
    const int tid = threadIdx.x, lane = tid & 31, wn = tid >> 5;
    const int m0 = blockIdx.x * BM;

    float acc[4][4][4];

    #pragma unroll 1
    for (int it = 0; it < 9; it++) {
        const int call = it - (it / 3) * 3;
        const int qpOff   = (call == 1) ? DIMQ : 0;
        const int colBase = (call == 1) ? 0 : DIMQ;
        const float coef  = (call == 1) ? DTC : -0.5f * DTC;

        // Stage 1: h1 = tanh(zp @ W1 + b1) -> X
        stage1_gemm(sb, g_zpb + (size_t)m0 * ZPD, acc, tid);
        EPI_BEGIN
            const float t0 = tanh_fast(v0 + __ldg(b1 + n));
            const float t1 = tanh_fast(v1 + __ldg(b1 + n + 1));
            *(__nv_bfloat162*)(smem + X_OFF + m * XPITCH + n * 2) = pack_bf2(t0, t1);
        EPI_END
        __syncthreads();

        // Stage 2: d2 = (1 - tanh(h1@W2 + b2)^2) * W3 -> Y
        gemm_res(sb, X_OFF, g_W2t, acc, lane, wn);
        EPI_BEGIN
            const float t0 = tanh_fast(v0 + __ldg(b2 + n));
            const float t1 = tanh_fast(v1 + __ldg(b2 + n + 1));
            const float r0 = (1.0f - t0 * t0) * __ldg(W3 + n);
            const float r1 = (1.0f - t1 * t1) * __ldg(W3 + n + 1);
            *(__nv_bfloat162*)(smem + Y_OFF + m * XPITCH + n * 2) = pack_bf2(r0, r1);
        EPI_END
        __syncthreads();

        // Stage 3: d1 = (d2 @ W2^T) * (1 - h1^2) -> X in-place (owner rmw)
        gemm_res(sb, Y_OFF, g_W2d, acc, lane, wn);
        EPI_BEGIN
            __nv_bfloat162* xp = (__nv_bfloat162*)(smem + X_OFF + m * XPITCH + n * 2);
            const __nv_bfloat162 hh = *xp;
            const float h0 = __bfloat162float(hh.x), h1v = __bfloat162float(hh.y);
            *xp = pack_bf2(v0 * (1.0f - h0 * h0), v1 * (1.0f - h1v * h1v));
        EPI_END
        __syncthreads();

        // Stage 4: g-half = d1 @ W1[qpOff..]^T, fused leapfrog zp update
        #pragma unroll 1
        for (int pass = 0; pass < 2; pass++) {
            gemm_res(sb, X_OFF, g_W1d + (size_t)(qpOff + pass * 256) * HID, acc, lane, wn);
            EPI_BEGIN
                const size_t o = (size_t)(m0 + m) * ZPD + colBase + pass * 256 + n;
                float2 z = *(float2*)(g_zp + o);
                z.x += coef * v0;
                z.y += coef * v1;
                *(float2*)(g_zp + o) = z;
                *(__nv_bfloat162*)(g_zpb + o) = pack_bf2(z.x, z.y);
            EPI_END
        }
        __syncthreads();   // call boundary: zp/zpb rows visible to next stage 1
    }
}

// ---------------- small kernels ----------------
__global__ void __launch_bounds__(256) prep_weights(const float* __restrict__ W1,
                                                    const float* __restrict__ W2)
{
    const int idx = blockIdx.x * 256 + threadIdx.x;     // 0 .. 262143
    {
        const int k = idx >> 8, n = idx & 255;
        const __nv_bfloat16 v = __float2bfloat16_rn(W1[idx]);
        g_W1d[idx] = v;
        g_W1t[n * ZPD + k] = v;
    }
    if (idx < HID * HID) {
        const int k = idx >> 8, n = idx & 255;
        const __nv_bfloat16 v = __float2bfloat16_rn(W2[idx]);
        g_W2d[idx] = v;
        g_W2t[n * HID + k] = v;
    }
}

__global__ void __launch_bounds__(256) init_zp(const float* __restrict__ z)
{
    const int i = blockIdx.x * 256 + threadIdx.x;       // over BATCH*DIMQ/4
    const int m = i / (DIMQ / 4);
    const int c = (i % (DIMQ / 4)) * 4;
    const float4 zv = *(const float4*)&z[(size_t)m * DIMQ + c];
    const size_t oq = (size_t)m * ZPD + c;
    const size_t op = oq + DIMQ;
    *(float4*)&g_zp[oq] = zv;
    *(float4*)&g_zp[op] = make_float4(0.f, 0.f, 0.f, 0.f);
    __nv_bfloat162 b01 = pack_bf2(zv.x, zv.y), b23 = pack_bf2(zv.z, zv.w);
    *(uint2*)&g_zpb[oq] = make_uint2(*(uint32_t*)&b01, *(uint32_t*)&b23);
    *(uint2*)&g_zpb[op] = make_uint2(0u, 0u);
}

__global__ void __launch_bounds__(256) write_out(float* __restrict__ out)
{
    const int i = blockIdx.x * 256 + threadIdx.x;
    const int m = i / (DIMQ / 4);
    const int c = (i % (DIMQ / 4)) * 4;
    *(float4*)&out[(size_t)m * DIMQ + c] = *(const float4*)&g_zp[(size_t)m * ZPD + c];
}

// ---------------- launcher ----------------
extern "C" void kernel_launch(void* const* d_in, const int* in_sizes, int n_in,
                              void* d_out, int out_size)
{
    const float* z  = (const float*)d_in[0];
    const float* W1 = (const float*)d_in[1];
    const float* b1 = (const float*)d_in[2];
    const float* W2 = (const float*)d_in[3];
    const float* b2 = (const float*)d_in[4];
    const float* W3 = (const float*)d_in[5];
    // d_in[6] = b3: constant, no gradient contribution.
    float* out = (float*)d_out;

    cudaFuncSetAttribute(leapfrog_all, cudaFuncAttributeMaxDynamicSharedMemorySize, SMEM_SZ);

    const dim3 blk(256);
    const dim3 grid_cp((BATCH * DIMQ / 4) / 256);

    init_zp<<<grid_cp, blk>>>(z);
    prep_weights<<<ZPD * HID / 256, blk>>>(W1, W2);
    leapfrog_all<<<BATCH / BM, blk, SMEM_SZ>>>(b1, b2, W3);
    write_out<<<grid_cp, blk>>>(out);
}